// round 14
// baseline (speedup 1.0000x reference)
#include <cuda_runtime.h>
#include <math.h>

// Problem dims
#define T_STEPS 2048
#define BATCH   16
#define TBROWS  (T_STEPS*BATCH)   // 32768
#define HD      512
#define PHD     1024
#define G3      1536
#define G4      2048
#define KSCALE  0.125f

// ---------------- scratch (static device arrays; no cudaMalloc) -----------
__device__ float g_up  [(size_t)TBROWS * PHD];
__device__ float g_qkvg[(size_t)TBROWS * 3072];
__device__ float g_h0  [(size_t)TBROWS * HD];
__device__ float g_wx  [(size_t)TBROWS * G4];
__device__ float g_h1  [(size_t)TBROWS * HD];
__device__ unsigned g_arrive;   // barrier arrival counter (zero-init)
__device__ unsigned g_phase;    // barrier phase (monotonic across replays)

// ---------------- generic fp32 SGEMM:  C[:, coff:coff+N] = act(A@W^T*alpha + bias)
#define BM 128
#define BN 128
#define BK 8

__global__ __launch_bounds__(256) void sgemm_kernel(
    const float* __restrict__ A, const float* __restrict__ W,
    float* __restrict__ C, int K, int ldc, int coff,
    const float* __restrict__ bias, float alpha, int act)
{
    __shared__ float As[BK][BM];
    __shared__ float Bs[BK][BN];

    const int tid = threadIdx.x;
    const int bx = blockIdx.x, by = blockIdx.y;
    const float* Ab = A + (size_t)by * BM * K;
    const float* Wb = W + (size_t)bx * BN * K;

    const int lrow = tid >> 1;
    const int lcol = (tid & 1) * 4;
    const int ty = tid >> 4, tx = tid & 15;

    float acc[8][8];
#pragma unroll
    for (int i = 0; i < 8; i++)
#pragma unroll
        for (int j = 0; j < 8; j++) acc[i][j] = 0.f;

    for (int k0 = 0; k0 < K; k0 += BK) {
        float4 a = *(const float4*)(Ab + (size_t)lrow * K + k0 + lcol);
        float4 w = *(const float4*)(Wb + (size_t)lrow * K + k0 + lcol);
        As[lcol + 0][lrow] = a.x; As[lcol + 1][lrow] = a.y;
        As[lcol + 2][lrow] = a.z; As[lcol + 3][lrow] = a.w;
        Bs[lcol + 0][lrow] = w.x; Bs[lcol + 1][lrow] = w.y;
        Bs[lcol + 2][lrow] = w.z; Bs[lcol + 3][lrow] = w.w;
        __syncthreads();
#pragma unroll
        for (int k = 0; k < BK; k++) {
            float4 a0 = *(const float4*)&As[k][ty * 8];
            float4 a1 = *(const float4*)&As[k][ty * 8 + 4];
            float4 b0 = *(const float4*)&Bs[k][tx * 8];
            float4 b1 = *(const float4*)&Bs[k][tx * 8 + 4];
            float ra[8] = {a0.x,a0.y,a0.z,a0.w,a1.x,a1.y,a1.z,a1.w};
            float rb[8] = {b0.x,b0.y,b0.z,b0.w,b1.x,b1.y,b1.z,b1.w};
#pragma unroll
            for (int i = 0; i < 8; i++)
#pragma unroll
                for (int j = 0; j < 8; j++)
                    acc[i][j] = fmaf(ra[i], rb[j], acc[i][j]);
        }
        __syncthreads();
    }

#pragma unroll
    for (int i = 0; i < 8; i++) {
        int row = by * BM + ty * 8 + i;
#pragma unroll
        for (int j = 0; j < 8; j++) {
            int col = bx * BN + tx * 8 + j;
            float v = acc[i][j] * alpha;
            if (bias) v += bias[col];
            if (act) v = v / (1.f + expf(-v));
            C[(size_t)row * ldc + coff + col] = v;
        }
    }
}

// ---------------- mLSTM elementwise scan ----------------------------------
__global__ __launch_bounds__(128) void mlstm_scan_kernel(
    const float* __restrict__ qkvg, float* __restrict__ hout)
{
    int idx = blockIdx.x * blockDim.x + threadIdx.x;   // 0..8191
    int b = idx >> 9, d = idx & 511;
    float c = 0.f, n = 0.f, m = 0.f;
    for (int t = 0; t < T_STEPS; t++) {
        const float* p = qkvg + ((size_t)t * BATCH + b) * 3072 + d;
        float q  = p[0];
        float k  = p[512];
        float v  = p[1024];
        float it = p[1536];
        float ft = p[2048];
        float ot = p[2560];
        float m2 = fmaxf(ft + m, it);
        float i  = expf(it - m2);
        float f  = expf(ft + m - m2);
        c = f * c + i * (v * k);
        n = f * n + i * k;
        m = m2;
        float den = fmaxf(fabsf(n * q), 1.0f);
        float h   = (1.f / (1.f + expf(-ot))) * (c * q) / den;
        hout[((size_t)t * BATCH + b) * HD + d] = h;
    }
}

// ---------------- persistent sLSTM (one launch per layer) -----------------
// 128 co-resident CTAs; CTA owns 4 h-dims (16 gate rows). R slice cached in
// smem for all 2048 steps. Grid barrier per step.
#define NCTA_S 128
#define HPAD   516   // h row pad (floats), 16B-aligned rows
#define RPAD   520   // R row pad

__device__ __forceinline__ void grid_bar()
{
    volatile unsigned* phase = &g_phase;
    __syncthreads();
    if (threadIdx.x == 0) {
        unsigned ph = *phase;
        __threadfence();
        unsigned old = atomicAdd(&g_arrive, 1u);
        if (old == NCTA_S - 1) {
            g_arrive = 0;
            __threadfence();
            *phase = ph + 1;
        } else {
            while (*phase == ph) { }
            __threadfence();
        }
    }
    __syncthreads();
}

__global__ __launch_bounds__(256) void slstm_persistent(
    const float* __restrict__ wx,   // [TB, 2048]  (Wx + bias precomputed)
    const float* __restrict__ Rs,   // [2048, 512]
    float* __restrict__ hbuf)       // [T, B, 512]
{
    extern __shared__ float smem[];
    float* R_sm   = smem;                       // [16][RPAD]
    float* h_sm   = R_sm + 16 * RPAD;           // [16][HPAD]
    float* gate_sm= h_sm + BATCH * HPAD;        // [16][16]

    const int tid = threadIdx.x;
    const int cta = blockIdx.x;                 // owns dims [cta*4, cta*4+4)
    const int r_local = tid >> 4;               // 0..15
    const int b = tid & 15;
    const int gate = r_local >> 2, dloc = r_local & 3;
    const int row = gate * HD + cta * 4 + dloc;

    // stage this CTA's 16 R rows into smem once
    for (int i = tid; i < 16 * HD; i += 256) {
        int rl = i >> 9, k = i & 511;
        int grow = (rl >> 2) * HD + cta * 4 + (rl & 3);
        R_sm[rl * RPAD + k] = Rs[(size_t)grow * HD + k];
    }
    // recurrent state in registers (valid for tid < 64)
    float c = 0.f, n = 0.f, m = 0.f;
    __syncthreads();

    for (int t = 0; t < T_STEPS; t++) {
        // stage h_{t-1}
        if (t > 0) {
            const float4* hprev = (const float4*)(hbuf + (size_t)(t - 1) * BATCH * HD);
            for (int i = tid; i < BATCH * HD / 4; i += 256) {
                int e = i * 4;
                int bi = e >> 9, k = e & 511;
                *(float4*)&h_sm[bi * HPAD + k] = hprev[i];
            }
        } else {
            for (int i = tid; i < BATCH * HPAD; i += 256) h_sm[i] = 0.f;
        }
        __syncthreads();

        // gate dot: thread (r_local, b)
        float acc = wx[((size_t)t * BATCH + b) * G4 + row];
        const float4* rp = (const float4*)(R_sm + r_local * RPAD);
        const float4* hp = (const float4*)(h_sm + b * HPAD);
#pragma unroll 8
        for (int k4 = 0; k4 < HD / 4; k4++) {
            float4 r = rp[k4];
            float4 h = hp[k4];
            acc = fmaf(r.x, h.x, acc);
            acc = fmaf(r.y, h.y, acc);
            acc = fmaf(r.z, h.z, acc);
            acc = fmaf(r.w, h.w, acc);
        }
        gate_sm[r_local * 16 + b] = acc;
        __syncthreads();

        if (tid < 64) {
            int b2 = tid & 15, dl = tid >> 4;   // dl 0..3
            float it = gate_sm[(0 + dl) * 16 + b2];
            float ft = gate_sm[(4 + dl) * 16 + b2];
            float zt = gate_sm[(8 + dl) * 16 + b2];
            float ot = gate_sm[(12 + dl) * 16 + b2];
            float m2 = fmaxf(ft + m, it);
            float i  = expf(it - m2);
            float f  = expf(ft + m - m2);
            c = f * c + i * tanhf(zt);
            n = f * n + i;
            m = m2;
            float h2 = (1.f / (1.f + expf(-ot))) * c / n;
            hbuf[((size_t)t * BATCH + b2) * HD + cta * 4 + dl] = h2;
        }
        grid_bar();   // publish h_t to all CTAs
    }
}

// ---------------- host orchestration --------------------------------------
extern "C" void kernel_launch(void* const* d_in, const int* in_sizes, int n_in,
                              void* d_out, int out_size)
{
    (void)in_sizes; (void)n_in; (void)out_size;
    const float* x    = (const float*)d_in[0];
    const float* Wup0 = (const float*)d_in[1];
    const float* Wq0  = (const float*)d_in[2];
    const float* Wk0  = (const float*)d_in[3];
    const float* Wv0  = (const float*)d_in[4];
    const float* Wg0  = (const float*)d_in[5];
    const float* bg0  = (const float*)d_in[6];
    const float* Ws1  = (const float*)d_in[7];
    const float* Rs1  = (const float*)d_in[8];
    const float* bs1  = (const float*)d_in[9];
    const float* Wup2 = (const float*)d_in[10];
    const float* Wq2  = (const float*)d_in[11];
    const float* Wk2  = (const float*)d_in[12];
    const float* Wv2  = (const float*)d_in[13];
    const float* Wg2  = (const float*)d_in[14];
    const float* bg2  = (const float*)d_in[15];
    const float* Ws3  = (const float*)d_in[16];
    const float* Rs3  = (const float*)d_in[17];
    const float* bs3  = (const float*)d_in[18];
    float* out = (float*)d_out;

    float *p_up, *p_qkvg, *p_h0, *p_wx, *p_h1;
    cudaGetSymbolAddress((void**)&p_up,   g_up);
    cudaGetSymbolAddress((void**)&p_qkvg, g_qkvg);
    cudaGetSymbolAddress((void**)&p_h0,   g_h0);
    cudaGetSymbolAddress((void**)&p_wx,   g_wx);
    cudaGetSymbolAddress((void**)&p_h1,   g_h1);

    const int slstm_smem = (16 * RPAD + BATCH * HPAD + 256) * sizeof(float);
    cudaFuncSetAttribute(slstm_persistent,
                         cudaFuncAttributeMaxDynamicSharedMemorySize, slstm_smem);

    const dim3 blk(256);
    const int MT = TBROWS / BM;

    // ---------- layer 0: mLSTM ----------
    sgemm_kernel<<<dim3(PHD / BN, MT), blk>>>(x, Wup0, p_up, HD, PHD, 0, nullptr, 1.f, 1);
    sgemm_kernel<<<dim3(HD  / BN, MT), blk>>>(p_up, Wq0, p_qkvg, PHD, 3072,    0, nullptr, 1.f,    0);
    sgemm_kernel<<<dim3(HD  / BN, MT), blk>>>(p_up, Wk0, p_qkvg, PHD, 3072,  512, nullptr, KSCALE, 0);
    sgemm_kernel<<<dim3(HD  / BN, MT), blk>>>(p_up, Wv0, p_qkvg, PHD, 3072, 1024, nullptr, 1.f,    0);
    sgemm_kernel<<<dim3(G3  / BN, MT), blk>>>(p_up, Wg0, p_qkvg, PHD, 3072, 1536, bg0,     1.f,    0);
    mlstm_scan_kernel<<<64, 128>>>(p_qkvg, p_h0);

    // ---------- layer 1: sLSTM ----------
    sgemm_kernel<<<dim3(G4 / BN, MT), blk>>>(p_h0, Ws1, p_wx, HD, G4, 0, bs1, 1.f, 0);
    slstm_persistent<<<NCTA_S, 256, slstm_smem>>>(p_wx, Rs1, p_h1);

    // ---------- layer 2: mLSTM ----------
    sgemm_kernel<<<dim3(PHD / BN, MT), blk>>>(p_h1, Wup2, p_up, HD, PHD, 0, nullptr, 1.f, 1);
    sgemm_kernel<<<dim3(HD  / BN, MT), blk>>>(p_up, Wq2, p_qkvg, PHD, 3072,    0, nullptr, 1.f,    0);
    sgemm_kernel<<<dim3(HD  / BN, MT), blk>>>(p_up, Wk2, p_qkvg, PHD, 3072,  512, nullptr, KSCALE, 0);
    sgemm_kernel<<<dim3(HD  / BN, MT), blk>>>(p_up, Wv2, p_qkvg, PHD, 3072, 1024, nullptr, 1.f,    0);
    sgemm_kernel<<<dim3(G3  / BN, MT), blk>>>(p_up, Wg2, p_qkvg, PHD, 3072, 1536, bg2,     1.f,    0);
    mlstm_scan_kernel<<<64, 128>>>(p_qkvg, p_h0);

    // ---------- layer 3: sLSTM -> d_out ----------
    sgemm_kernel<<<dim3(G4 / BN, MT), blk>>>(p_h0, Ws3, p_wx, HD, G4, 0, bs3, 1.f, 0);
    slstm_persistent<<<NCTA_S, 256, slstm_smem>>>(p_wx, Rs3, out);
}

// round 15
// speedup vs baseline: 1.0461x; 1.0461x over previous
#include <cuda_runtime.h>
#include <math.h>

// Problem dims
#define T_STEPS 2048
#define BATCH   16
#define TBROWS  (T_STEPS*BATCH)   // 32768
#define HD      512
#define PHD     1024
#define G3      1536
#define G4      2048
#define KSCALE  0.125f

// ---------------- scratch (static device arrays; no cudaMalloc) -----------
__device__ float g_up  [(size_t)TBROWS * PHD];
__device__ float g_qkvg[(size_t)TBROWS * 3072];
__device__ float g_h0  [(size_t)TBROWS * HD];
__device__ float g_wx  [(size_t)TBROWS * G4];
__device__ float g_h1  [(size_t)TBROWS * HD];
__device__ unsigned g_arrive;   // barrier arrival counter (zero-init)
__device__ unsigned g_phase;    // barrier phase (monotonic across replays)

// ---------------- generic fp32 SGEMM:  C[:, coff:coff+N] = act(A@W^T*alpha + bias)
#define BM 128
#define BN 128
#define BK 8

__global__ __launch_bounds__(256) void sgemm_kernel(
    const float* __restrict__ A, const float* __restrict__ W,
    float* __restrict__ C, int K, int ldc, int coff,
    const float* __restrict__ bias, float alpha, int act)
{
    __shared__ float As[BK][BM];
    __shared__ float Bs[BK][BN];

    const int tid = threadIdx.x;
    const int bx = blockIdx.x, by = blockIdx.y;
    const float* Ab = A + (size_t)by * BM * K;
    const float* Wb = W + (size_t)bx * BN * K;

    const int lrow = tid >> 1;
    const int lcol = (tid & 1) * 4;
    const int ty = tid >> 4, tx = tid & 15;

    float acc[8][8];
#pragma unroll
    for (int i = 0; i < 8; i++)
#pragma unroll
        for (int j = 0; j < 8; j++) acc[i][j] = 0.f;

    for (int k0 = 0; k0 < K; k0 += BK) {
        float4 a = *(const float4*)(Ab + (size_t)lrow * K + k0 + lcol);
        float4 w = *(const float4*)(Wb + (size_t)lrow * K + k0 + lcol);
        As[lcol + 0][lrow] = a.x; As[lcol + 1][lrow] = a.y;
        As[lcol + 2][lrow] = a.z; As[lcol + 3][lrow] = a.w;
        Bs[lcol + 0][lrow] = w.x; Bs[lcol + 1][lrow] = w.y;
        Bs[lcol + 2][lrow] = w.z; Bs[lcol + 3][lrow] = w.w;
        __syncthreads();
#pragma unroll
        for (int k = 0; k < BK; k++) {
            float4 a0 = *(const float4*)&As[k][ty * 8];
            float4 a1 = *(const float4*)&As[k][ty * 8 + 4];
            float4 b0 = *(const float4*)&Bs[k][tx * 8];
            float4 b1 = *(const float4*)&Bs[k][tx * 8 + 4];
            float ra[8] = {a0.x,a0.y,a0.z,a0.w,a1.x,a1.y,a1.z,a1.w};
            float rb[8] = {b0.x,b0.y,b0.z,b0.w,b1.x,b1.y,b1.z,b1.w};
#pragma unroll
            for (int i = 0; i < 8; i++)
#pragma unroll
                for (int j = 0; j < 8; j++)
                    acc[i][j] = fmaf(ra[i], rb[j], acc[i][j]);
        }
        __syncthreads();
    }

#pragma unroll
    for (int i = 0; i < 8; i++) {
        int row = by * BM + ty * 8 + i;
#pragma unroll
        for (int j = 0; j < 8; j++) {
            int col = bx * BN + tx * 8 + j;
            float v = acc[i][j] * alpha;
            if (bias) v += bias[col];
            if (act) v = v / (1.f + expf(-v));
            C[(size_t)row * ldc + coff + col] = v;
        }
    }
}

// ---------------- mLSTM elementwise scan ----------------------------------
__global__ __launch_bounds__(128) void mlstm_scan_kernel(
    const float* __restrict__ qkvg, float* __restrict__ hout)
{
    int idx = blockIdx.x * blockDim.x + threadIdx.x;   // 0..8191
    int b = idx >> 9, d = idx & 511;
    float c = 0.f, n = 0.f, m = 0.f;
    for (int t = 0; t < T_STEPS; t++) {
        const float* p = qkvg + ((size_t)t * BATCH + b) * 3072 + d;
        float q  = p[0];
        float k  = p[512];
        float v  = p[1024];
        float it = p[1536];
        float ft = p[2048];
        float ot = p[2560];
        float m2 = fmaxf(ft + m, it);
        float i  = expf(it - m2);
        float f  = expf(ft + m - m2);
        c = f * c + i * (v * k);
        n = f * n + i * k;
        m = m2;
        float den = fmaxf(fabsf(n * q), 1.0f);
        float h   = (1.f / (1.f + expf(-ot))) * (c * q) / den;
        hout[((size_t)t * BATCH + b) * HD + d] = h;
    }
}

// ---------------- persistent sLSTM (one launch per layer) -----------------
// 128 co-resident CTAs; CTA owns 4 h-dims (16 gate rows). R slice cached in
// smem for all 2048 steps. Grid barrier per step.
#define NCTA_S 128
#define HPAD   516   // h row pad (floats), 16B-aligned rows
#define RPAD   520   // R row pad

__device__ __forceinline__ void grid_bar()
{
    volatile unsigned* phase = &g_phase;
    __syncthreads();
    if (threadIdx.x == 0) {
        unsigned ph = *phase;
        __threadfence();
        unsigned old = atomicAdd(&g_arrive, 1u);
        if (old == NCTA_S - 1) {
            g_arrive = 0;
            __threadfence();
            *phase = ph + 1;
        } else {
            while (*phase == ph) { }
            __threadfence();
        }
    }
    __syncthreads();
}

__global__ __launch_bounds__(256) void slstm_persistent(
    const float* __restrict__ wx,   // [TB, 2048]  (Wx + bias precomputed)
    const float* __restrict__ Rs,   // [2048, 512]
    float* __restrict__ hbuf)       // [T, B, 512]
{
    extern __shared__ float smem[];
    float* R_sm   = smem;                       // [16][RPAD]
    float* h_sm   = R_sm + 16 * RPAD;           // [16][HPAD]
    float* gate_sm= h_sm + BATCH * HPAD;        // [16][16]

    const int tid = threadIdx.x;
    const int cta = blockIdx.x;                 // owns dims [cta*4, cta*4+4)
    const int r_local = tid >> 4;               // 0..15
    const int b = tid & 15;
    const int gate = r_local >> 2, dloc = r_local & 3;
    const int row = gate * HD + cta * 4 + dloc;

    // stage this CTA's 16 R rows into smem once
    for (int i = tid; i < 16 * HD; i += 256) {
        int rl = i >> 9, k = i & 511;
        int grow = (rl >> 2) * HD + cta * 4 + (rl & 3);
        R_sm[rl * RPAD + k] = Rs[(size_t)grow * HD + k];
    }
    // recurrent state in registers (valid for tid < 64)
    float c = 0.f, n = 0.f, m = 0.f;
    __syncthreads();

    for (int t = 0; t < T_STEPS; t++) {
        // stage h_{t-1}
        if (t > 0) {
            const float4* hprev = (const float4*)(hbuf + (size_t)(t - 1) * BATCH * HD);
            for (int i = tid; i < BATCH * HD / 4; i += 256) {
                int e = i * 4;
                int bi = e >> 9, k = e & 511;
                *(float4*)&h_sm[bi * HPAD + k] = hprev[i];
            }
        } else {
            for (int i = tid; i < BATCH * HPAD; i += 256) h_sm[i] = 0.f;
        }
        __syncthreads();

        // gate dot: thread (r_local, b)
        float acc = wx[((size_t)t * BATCH + b) * G4 + row];
        const float4* rp = (const float4*)(R_sm + r_local * RPAD);
        const float4* hp = (const float4*)(h_sm + b * HPAD);
#pragma unroll 8
        for (int k4 = 0; k4 < HD / 4; k4++) {
            float4 r = rp[k4];
            float4 h = hp[k4];
            acc = fmaf(r.x, h.x, acc);
            acc = fmaf(r.y, h.y, acc);
            acc = fmaf(r.z, h.z, acc);
            acc = fmaf(r.w, h.w, acc);
        }
        gate_sm[r_local * 16 + b] = acc;
        __syncthreads();

        if (tid < 64) {
            int b2 = tid & 15, dl = tid >> 4;   // dl 0..3
            float it = gate_sm[(0 + dl) * 16 + b2];
            float ft = gate_sm[(4 + dl) * 16 + b2];
            float zt = gate_sm[(8 + dl) * 16 + b2];
            float ot = gate_sm[(12 + dl) * 16 + b2];
            float m2 = fmaxf(ft + m, it);
            float i  = expf(it - m2);
            float f  = expf(ft + m - m2);
            c = f * c + i * tanhf(zt);
            n = f * n + i;
            m = m2;
            float h2 = (1.f / (1.f + expf(-ot))) * c / n;
            hbuf[((size_t)t * BATCH + b2) * HD + cta * 4 + dl] = h2;
        }
        grid_bar();   // publish h_t to all CTAs
    }
}

// ---------------- host orchestration --------------------------------------
extern "C" void kernel_launch(void* const* d_in, const int* in_sizes, int n_in,
                              void* d_out, int out_size)
{
    (void)in_sizes; (void)n_in; (void)out_size;
    const float* x    = (const float*)d_in[0];
    const float* Wup0 = (const float*)d_in[1];
    const float* Wq0  = (const float*)d_in[2];
    const float* Wk0  = (const float*)d_in[3];
    const float* Wv0  = (const float*)d_in[4];
    const float* Wg0  = (const float*)d_in[5];
    const float* bg0  = (const float*)d_in[6];
    const float* Ws1  = (const float*)d_in[7];
    const float* Rs1  = (const float*)d_in[8];
    const float* bs1  = (const float*)d_in[9];
    const float* Wup2 = (const float*)d_in[10];
    const float* Wq2  = (const float*)d_in[11];
    const float* Wk2  = (const float*)d_in[12];
    const float* Wv2  = (const float*)d_in[13];
    const float* Wg2  = (const float*)d_in[14];
    const float* bg2  = (const float*)d_in[15];
    const float* Ws3  = (const float*)d_in[16];
    const float* Rs3  = (const float*)d_in[17];
    const float* bs3  = (const float*)d_in[18];
    float* out = (float*)d_out;

    float *p_up, *p_qkvg, *p_h0, *p_wx, *p_h1;
    cudaGetSymbolAddress((void**)&p_up,   g_up);
    cudaGetSymbolAddress((void**)&p_qkvg, g_qkvg);
    cudaGetSymbolAddress((void**)&p_h0,   g_h0);
    cudaGetSymbolAddress((void**)&p_wx,   g_wx);
    cudaGetSymbolAddress((void**)&p_h1,   g_h1);

    const int slstm_smem = (16 * RPAD + BATCH * HPAD + 256) * sizeof(float);
    cudaFuncSetAttribute(slstm_persistent,
                         cudaFuncAttributeMaxDynamicSharedMemorySize, slstm_smem);

    const dim3 blk(256);
    const int MT = TBROWS / BM;

    // ---------- layer 0: mLSTM ----------
    sgemm_kernel<<<dim3(PHD / BN, MT), blk>>>(x, Wup0, p_up, HD, PHD, 0, nullptr, 1.f, 1);
    sgemm_kernel<<<dim3(HD  / BN, MT), blk>>>(p_up, Wq0, p_qkvg, PHD, 3072,    0, nullptr, 1.f,    0);
    sgemm_kernel<<<dim3(HD  / BN, MT), blk>>>(p_up, Wk0, p_qkvg, PHD, 3072,  512, nullptr, KSCALE, 0);
    sgemm_kernel<<<dim3(HD  / BN, MT), blk>>>(p_up, Wv0, p_qkvg, PHD, 3072, 1024, nullptr, 1.f,    0);
    sgemm_kernel<<<dim3(G3  / BN, MT), blk>>>(p_up, Wg0, p_qkvg, PHD, 3072, 1536, bg0,     1.f,    0);
    mlstm_scan_kernel<<<64, 128>>>(p_qkvg, p_h0);

    // ---------- layer 1: sLSTM ----------
    sgemm_kernel<<<dim3(G4 / BN, MT), blk>>>(p_h0, Ws1, p_wx, HD, G4, 0, bs1, 1.f, 0);
    slstm_persistent<<<NCTA_S, 256, slstm_smem>>>(p_wx, Rs1, p_h1);

    // ---------- layer 2: mLSTM ----------
    sgemm_kernel<<<dim3(PHD / BN, MT), blk>>>(p_h1, Wup2, p_up, HD, PHD, 0, nullptr, 1.f, 1);
    sgemm_kernel<<<dim3(HD  / BN, MT), blk>>>(p_up, Wq2, p_qkvg, PHD, 3072,    0, nullptr, 1.f,    0);
    sgemm_kernel<<<dim3(HD  / BN, MT), blk>>>(p_up, Wk2, p_qkvg, PHD, 3072,  512, nullptr, KSCALE, 0);
    sgemm_kernel<<<dim3(HD  / BN, MT), blk>>>(p_up, Wv2, p_qkvg, PHD, 3072, 1024, nullptr, 1.f,    0);
    sgemm_kernel<<<dim3(G3  / BN, MT), blk>>>(p_up, Wg2, p_qkvg, PHD, 3072, 1536, bg2,     1.f,    0);
    mlstm_scan_kernel<<<64, 128>>>(p_qkvg, p_h0);

    // ---------- layer 3: sLSTM -> d_out ----------
    sgemm_kernel<<<dim3(G4 / BN, MT), blk>>>(p_h0, Ws3, p_wx, HD, G4, 0, bs3, 1.f, 0);
    slstm_persistent<<<NCTA_S, 256, slstm_smem>>>(p_wx, Rs3, out);
}